// round 1
// baseline (speedup 1.0000x reference)
#include <cuda_runtime.h>

// Problem constants
constexpr int C_   = 192;
constexpr int H_   = 192;
constexpr int W_   = 192;
constexpr int SS_  = 4;
constexpr int NH_  = 6;
constexpr int NWIN = 8 * 24 * 24;   // 4608 windows total
constexpr int HW_  = H_ * W_;       // 36864

// Scratch (device globals: allocation-free rule)
__device__ float g_qkv[NWIN * 3 * NH_ * 64 * 32];  // [b_][s][h][n][d]
__device__ float g_att[NWIN * 64 * 192];           // [b_*64+n][c]

// ---------- packed f32x2 helpers ----------
__device__ __forceinline__ unsigned long long pk2(float x, float y) {
    unsigned long long r;
    asm("mov.b64 %0, {%1,%2};" : "=l"(r) : "f"(x), "f"(y));
    return r;
}
__device__ __forceinline__ void upk2(unsigned long long v, float& x, float& y) {
    asm("mov.b64 {%0,%1}, %2;" : "=f"(x), "=f"(y) : "l"(v));
}
__device__ __forceinline__ unsigned long long ffma2(unsigned long long a,
                                                    unsigned long long b,
                                                    unsigned long long c) {
    unsigned long long d;
    asm("fma.rn.f32x2 %0, %1, %2, %3;" : "=l"(d) : "l"(a), "l"(b), "l"(c));
    return d;
}

// =====================================================================
// Kernel 1: gather rolled window + QKV projection
// grid = 4608, block = 256, dyn smem = (192*64 + 192*66)*4 = 99840 B
// =====================================================================
__global__ __launch_bounds__(256, 2)
void k_qkv(const float* __restrict__ x, const float* __restrict__ w,
           const float* __restrict__ bias) {
    extern __shared__ float sm[];
    float* xs  = sm;               // [192][64]  (k-major, token minor)
    float* wsm = sm + 192 * 64;    // [192][66]  (k-major, out minor, pad 66)
    float* res = wsm;              // reused as [64][65] staging

    const int b_  = blockIdx.x;
    const int b   = b_ / 576;
    const int wh  = (b_ % 576) / 24;
    const int ww  = b_ % 24;
    const int tid = threadIdx.x;

    __shared__ int soff[64];
    if (tid < 64) {
        int ph = tid >> 3, pw = tid & 7;
        int sh = wh * 8 + ph + SS_; if (sh >= H_) sh -= H_;
        int sw = ww * 8 + pw + SS_; if (sw >= W_) sw -= W_;
        soff[tid] = sh * W_ + sw;
    }
    __syncthreads();

    // Load window (64 tokens x 192 channels), transposed into xs[k][t]
    const float* xb = x + (long)b * (C_ * HW_);
    #pragma unroll 4
    for (int idx = tid; idx < 192 * 64; idx += 256) {
        int c = idx >> 6, t = idx & 63;
        xs[c * 64 + t] = xb[c * HW_ + soff[t]];
    }

    const int ty = tid >> 3, tx = tid & 7;
    const int t0 = ty * 2;

    for (int ch = 0; ch < 9; ch++) {
        __syncthreads();  // res (aliased on wsm) fully consumed
        // Load weight chunk (64 outputs x 192 k), transposed
        const float* wb = w + ch * 64 * 192;
        #pragma unroll 4
        for (int idx = tid; idx < 64 * 192; idx += 256) {
            int o = idx / 192, k = idx - o * 192;
            wsm[k * 66 + o] = wb[o * 192 + k];
        }
        __syncthreads();

        const int obase = ch * 64 + tx * 8;
        unsigned long long acc0[4], acc1[4];
        #pragma unroll
        for (int j = 0; j < 4; j++) {
            unsigned long long bb =
                *(const unsigned long long*)&bias[obase + 2 * j];
            acc0[j] = bb; acc1[j] = bb;
        }
        #pragma unroll 4
        for (int k = 0; k < 192; k++) {
            float ax, ay;
            unsigned long long av =
                *(const unsigned long long*)&xs[k * 64 + t0];
            upk2(av, ax, ay);
            unsigned long long a0 = pk2(ax, ax), a1 = pk2(ay, ay);
            const unsigned long long* wr =
                (const unsigned long long*)&wsm[k * 66 + tx * 8];
            #pragma unroll
            for (int j = 0; j < 4; j++) {
                unsigned long long bv = wr[j];
                acc0[j] = ffma2(a0, bv, acc0[j]);
                acc1[j] = ffma2(a1, bv, acc1[j]);
            }
        }
        __syncthreads();  // all wsm reads done before aliased res writes

        #pragma unroll
        for (int j = 0; j < 4; j++) {
            float x0, y0, x1, y1;
            upk2(acc0[j], x0, y0);
            upk2(acc1[j], x1, y1);
            int ol = tx * 8 + 2 * j;
            res[ol * 65 + t0]           = x0;
            res[(ol + 1) * 65 + t0]     = y0;
            res[ol * 65 + t0 + 1]       = x1;
            res[(ol + 1) * 65 + t0 + 1] = y1;
        }
        __syncthreads();

        // Scatter chunk into g_qkv [b_][s][h][n][d] (coalesced: d fastest)
        #pragma unroll
        for (int it = 0; it < 16; it++) {
            int idx = tid + it * 256;
            int shl = idx >> 11;
            int t   = (idx >> 5) & 63;
            int d   = idx & 31;
            int shg = ch * 2 + shl;
            int s   = shg / 6, h = shg - 6 * s;
            float v = res[(shl * 32 + d) * 65 + t];
            if (s == 0) v *= 0.17677669529663687f;  // 32^-0.5
            g_qkv[((((long)b_ * 3 + s) * 6 + h) * 64 + t) * 32 + d] = v;
        }
    }
}

// =====================================================================
// Kernel 2: windowed attention (one CTA per (window, head))
// grid = (4608, 6), block = 64
// =====================================================================
__global__ __launch_bounds__(64)
void k_attn(const float* __restrict__ tbl) {
    __shared__ float ks[64 * 32];
    __shared__ float vs[64 * 32];
    __shared__ float ss[64 * 65];
    __shared__ float tb[225];
    __shared__ int   ids[64];

    const int b_ = blockIdx.x;
    const int h  = blockIdx.y;
    const int wh = (b_ % 576) / 24;
    const int ww = b_ % 24;
    const int n  = threadIdx.x;

    const float* qp = g_qkv + ((((long)b_ * 3 + 0) * 6 + h) * 64 + n) * 32;
    const float* kp = g_qkv + ((((long)b_ * 3 + 1) * 6 + h) * 64 + n) * 32;
    const float* vp = g_qkv + ((((long)b_ * 3 + 2) * 6 + h) * 64 + n) * 32;

    float4 q4[8];
    #pragma unroll
    for (int i = 0; i < 8; i++) q4[i] = ((const float4*)qp)[i];
    #pragma unroll
    for (int i = 0; i < 8; i++) ((float4*)&ks[n * 32])[i] = ((const float4*)kp)[i];
    #pragma unroll
    for (int i = 0; i < 8; i++) ((float4*)&vs[n * 32])[i] = ((const float4*)vp)[i];

    {
        int ph = n >> 3, pw = n & 7;
        int gh = wh * 8 + ph, gw = ww * 8 + pw;
        int rh = gh < (H_ - 8) ? 0 : (gh < (H_ - 4) ? 1 : 2);
        int rw = gw < (W_ - 8) ? 0 : (gw < (W_ - 4) ? 1 : 2);
        ids[n] = rh * 3 + rw;
    }
    for (int i = n; i < 225; i += 64) tb[i] = tbl[i * 6 + h];
    __syncthreads();

    const int ihn = n >> 3, iwn = n & 7;
    const int idn = ids[n];
    float mx = -1e30f;
    #pragma unroll 2
    for (int m = 0; m < 64; m++) {
        const float4* kr = (const float4*)&ks[m * 32];
        float d0 = 0.f, d1 = 0.f, d2 = 0.f, d3 = 0.f;
        #pragma unroll
        for (int i = 0; i < 8; i++) {
            float4 kv = kr[i];
            d0 = fmaf(q4[i].x, kv.x, d0);
            d1 = fmaf(q4[i].y, kv.y, d1);
            d2 = fmaf(q4[i].z, kv.z, d2);
            d3 = fmaf(q4[i].w, kv.w, d3);
        }
        float dot  = (d0 + d1) + (d2 + d3);
        int   idxb = (ihn - (m >> 3) + 7) * 15 + (iwn - (m & 7) + 7);
        float sv   = dot + tb[idxb];
        if (idn != ids[m]) sv -= 100.0f;
        ss[n * 65 + m] = sv;
        mx = fmaxf(mx, sv);
    }

    float sum = 0.0f;
    float4 acc[8];
    #pragma unroll
    for (int i = 0; i < 8; i++) acc[i] = make_float4(0.f, 0.f, 0.f, 0.f);
    #pragma unroll 2
    for (int m = 0; m < 64; m++) {
        float e = __expf(ss[n * 65 + m] - mx);
        sum += e;
        const float4* vr = (const float4*)&vs[m * 32];
        #pragma unroll
        for (int i = 0; i < 8; i++) {
            float4 vv = vr[i];
            acc[i].x = fmaf(e, vv.x, acc[i].x);
            acc[i].y = fmaf(e, vv.y, acc[i].y);
            acc[i].z = fmaf(e, vv.z, acc[i].z);
            acc[i].w = fmaf(e, vv.w, acc[i].w);
        }
    }
    float inv = 1.0f / sum;
    float* op = g_att + ((long)b_ * 64 + n) * 192 + h * 32;
    #pragma unroll
    for (int i = 0; i < 8; i++) {
        float4 o = acc[i];
        o.x *= inv; o.y *= inv; o.z *= inv; o.w *= inv;
        ((float4*)op)[i] = o;
    }
}

// =====================================================================
// Kernel 3: output projection + window-reverse + reverse roll scatter
// grid = 4608, block = 256, dyn smem = (192*66)*2*4 = 101376 B
// =====================================================================
__global__ __launch_bounds__(256, 2)
void k_proj(const float* __restrict__ w, const float* __restrict__ bias,
            float* __restrict__ out) {
    extern __shared__ float sm[];
    float* as  = sm;               // [192][66] (c-major, token minor)
    float* wsm = sm + 192 * 66;    // [192][66], reused as res[64][65]
    float* res = wsm;

    const int b_  = blockIdx.x;
    const int b   = b_ / 576;
    const int wh  = (b_ % 576) / 24;
    const int ww  = b_ % 24;
    const int tid = threadIdx.x;

    __shared__ int soff[64];
    if (tid < 64) {
        int ph = tid >> 3, pw = tid & 7;
        int sh = wh * 8 + ph + SS_; if (sh >= H_) sh -= H_;
        int sw = ww * 8 + pw + SS_; if (sw >= W_) sw -= W_;
        soff[tid] = sh * W_ + sw;
    }
    __syncthreads();

    const float* ab = g_att + (long)b_ * 64 * 192;
    #pragma unroll 4
    for (int idx = tid; idx < 64 * 192; idx += 256) {
        int t = idx / 192, c = idx - t * 192;
        as[c * 66 + t] = ab[idx];
    }

    const int ty = tid >> 3, tx = tid & 7;
    const int t0 = ty * 2;
    float* outb = out + (long)b * (C_ * HW_);

    for (int ch = 0; ch < 3; ch++) {
        __syncthreads();
        const float* wb = w + ch * 64 * 192;
        #pragma unroll 4
        for (int idx = tid; idx < 64 * 192; idx += 256) {
            int o = idx / 192, k = idx - o * 192;
            wsm[k * 66 + o] = wb[o * 192 + k];
        }
        __syncthreads();

        const int obase = ch * 64 + tx * 8;
        unsigned long long acc0[4], acc1[4];
        #pragma unroll
        for (int j = 0; j < 4; j++) {
            unsigned long long bb =
                *(const unsigned long long*)&bias[obase + 2 * j];
            acc0[j] = bb; acc1[j] = bb;
        }
        #pragma unroll 4
        for (int k = 0; k < 192; k++) {
            float ax, ay;
            unsigned long long av =
                *(const unsigned long long*)&as[k * 66 + t0];
            upk2(av, ax, ay);
            unsigned long long a0 = pk2(ax, ax), a1 = pk2(ay, ay);
            const unsigned long long* wr =
                (const unsigned long long*)&wsm[k * 66 + tx * 8];
            #pragma unroll
            for (int j = 0; j < 4; j++) {
                unsigned long long bv = wr[j];
                acc0[j] = ffma2(a0, bv, acc0[j]);
                acc1[j] = ffma2(a1, bv, acc1[j]);
            }
        }
        __syncthreads();

        #pragma unroll
        for (int j = 0; j < 4; j++) {
            float x0, y0, x1, y1;
            upk2(acc0[j], x0, y0);
            upk2(acc1[j], x1, y1);
            int ol = tx * 8 + 2 * j;
            res[ol * 65 + t0]           = x0;
            res[(ol + 1) * 65 + t0]     = y0;
            res[ol * 65 + t0 + 1]       = x1;
            res[(ol + 1) * 65 + t0 + 1] = y1;
        }
        __syncthreads();

        #pragma unroll
        for (int it = 0; it < 16; it++) {
            int idx = tid + it * 256;
            int o = idx >> 6, t = idx & 63;
            outb[(ch * 64 + o) * HW_ + soff[t]] = res[o * 65 + t];
        }
    }
}

// =====================================================================
extern "C" void kernel_launch(void* const* d_in, const int* in_sizes, int n_in,
                              void* d_out, int out_size) {
    const float* x      = (const float*)d_in[0];
    const float* qkv_w  = (const float*)d_in[1];
    const float* qkv_b  = (const float*)d_in[2];
    const float* proj_w = (const float*)d_in[3];
    const float* proj_b = (const float*)d_in[4];
    const float* tbl    = (const float*)d_in[5];
    float* out = (float*)d_out;

    // Idempotent attribute setup (no allocation, capture-safe, deterministic)
    cudaFuncSetAttribute(k_qkv,  cudaFuncAttributeMaxDynamicSharedMemorySize, 102400);
    cudaFuncSetAttribute(k_proj, cudaFuncAttributeMaxDynamicSharedMemorySize, 102400);

    k_qkv<<<NWIN, 256, (192 * 64 + 192 * 66) * 4>>>(x, qkv_w, qkv_b);
    k_attn<<<dim3(NWIN, NH_), 64>>>(tbl);
    k_proj<<<NWIN, 256, (192 * 66 * 2) * 4>>>(proj_w, proj_b, out);
}

// round 2
// speedup vs baseline: 2.3111x; 2.3111x over previous
#include <cuda_runtime.h>

constexpr int C_   = 192;
constexpr int H_   = 192;
constexpr int W_   = 192;
constexpr int SS_  = 4;
constexpr int NH_  = 6;
constexpr int NWIN = 8 * 24 * 24;   // 4608
constexpr int HW_  = H_ * W_;

__device__ float g_qkv[(size_t)NWIN * 3 * NH_ * 64 * 32];  // [b_][s][h][n][d]
__device__ float g_att[(size_t)NWIN * 64 * 192];           // [b_*64+n][c]

typedef unsigned long long ull;

__device__ __forceinline__ ull dup2(float x) {
    ull r; asm("mov.b64 %0,{%1,%1};" : "=l"(r) : "f"(x)); return r;
}
__device__ __forceinline__ void upk2(ull v, float& x, float& y) {
    asm("mov.b64 {%0,%1},%2;" : "=f"(x), "=f"(y) : "l"(v));
}
__device__ __forceinline__ ull ffma2(ull a, ull b, ull c) {
    ull d; asm("fma.rn.f32x2 %0,%1,%2,%3;" : "=l"(d) : "l"(a), "l"(b), "l"(c));
    return d;
}

// =====================================================================
// Kernel 1: gather rolled window + QKV projection
// grid=4608, block=256. smem: xs[192][64] + wsm[192][194] = 198144 B
// Per-thread tile: 4 tokens x 12 outputs (o = 2*tx + 32*j)
// =====================================================================
__global__ __launch_bounds__(256, 1)
void k_qkv(const float* __restrict__ x, const float* __restrict__ w,
           const float* __restrict__ bias) {
    extern __shared__ float sm[];
    float* xs  = sm;               // [192][64]
    float* wsm = sm + 192 * 64;    // [192][194]
    __shared__ int soff[64];

    const int b_  = blockIdx.x;
    const int b   = b_ / 576;
    const int wh  = (b_ % 576) / 24;
    const int ww  = b_ % 24;
    const int tid = threadIdx.x;

    if (tid < 64) {
        int ph = tid >> 3, pw = tid & 7;
        int sh = wh * 8 + ph + SS_; if (sh >= H_) sh -= H_;
        int sw = ww * 8 + pw + SS_; if (sw >= W_) sw -= W_;
        soff[tid] = sh * W_ + sw;
    }
    __syncthreads();

    const float* xb = x + (size_t)b * C_ * HW_;
    #pragma unroll
    for (int i = 0; i < 48; i++) {
        int idx = tid + i * 256;
        int c = idx >> 6, t = idx & 63;
        xs[c * 64 + t] = xb[c * HW_ + soff[t]];
    }

    const int ty = tid >> 4, tx = tid & 15, t0 = ty * 4;
    float* gout = g_qkv + (size_t)b_ * 3 * 6 * 64 * 32;

    for (int s = 0; s < 3; s++) {
        __syncthreads();
        const float* wb = w + s * 192 * 192;
        #pragma unroll
        for (int i = 0; i < 144; i++) {
            int idx = tid + i * 256;
            int o = idx / 192, k = idx - o * 192;
            wsm[k * 194 + o] = wb[o * 192 + k];
        }
        __syncthreads();

        ull acc[4][6];
        #pragma unroll
        for (int j = 0; j < 6; j++) {
            ull bb = *(const ull*)&bias[s * 192 + 2 * tx + 32 * j];
            #pragma unroll
            for (int t = 0; t < 4; t++) acc[t][j] = bb;
        }

        #pragma unroll 2
        for (int k = 0; k < 192; k++) {
            float4 af = *(const float4*)&xs[k * 64 + t0];
            ull a0 = dup2(af.x), a1 = dup2(af.y), a2 = dup2(af.z), a3 = dup2(af.w);
            const ull* wr = (const ull*)&wsm[k * 194 + 2 * tx];
            #pragma unroll
            for (int j = 0; j < 6; j++) {
                ull bv = wr[16 * j];
                acc[0][j] = ffma2(a0, bv, acc[0][j]);
                acc[1][j] = ffma2(a1, bv, acc[1][j]);
                acc[2][j] = ffma2(a2, bv, acc[2][j]);
                acc[3][j] = ffma2(a3, bv, acc[3][j]);
            }
        }

        const float sc = (s == 0) ? 0.17677669529663687f : 1.0f;
        float* go = gout + (size_t)s * 6 * 64 * 32;
        #pragma unroll
        for (int j = 0; j < 6; j++) {
            #pragma unroll
            for (int t = 0; t < 4; t++) {
                float xx, yy;
                upk2(acc[t][j], xx, yy);
                float2 v; v.x = xx * sc; v.y = yy * sc;
                *(float2*)&go[(j * 64 + t0 + t) * 32 + 2 * tx] = v;
            }
        }
    }
}

// =====================================================================
// Kernel 2: fused single-pass windowed attention
// grid=4608, block=192 (warp h, lane r handles query rows r and r+32)
// smem: ks[6][64][32] + vs[6][64][32] + tb[6][228] + ids[64] = 104032 B
// No max-subtraction: logits in [-100, ~1]; expf exact, mask -> 0.
// =====================================================================
__global__ __launch_bounds__(192, 2)
void k_attn(const float* __restrict__ tbl) {
    extern __shared__ float sm[];
    float* ks = sm;               // 12288 floats
    float* vs = sm + 12288;       // 12288 floats
    float* tb = sm + 24576;       // 6*228
    int*  ids = (int*)(sm + 24576 + 1368);

    const int b_  = blockIdx.x;
    const int wh  = (b_ % 576) / 24;
    const int ww  = b_ % 24;
    const int tid = threadIdx.x;
    const int h   = tid >> 5;
    const int r   = tid & 31;

    const float* base = g_qkv + (size_t)b_ * 3 * 12288;

    {   // cooperative K/V copies (fully coalesced, layout match)
        const float4* srck = (const float4*)(base + 12288);
        const float4* srcv = (const float4*)(base + 24576);
        float4* dk = (float4*)ks;
        float4* dv = (float4*)vs;
        #pragma unroll
        for (int i = 0; i < 16; i++) {
            int idx = tid + i * 192;
            dk[idx] = srck[idx];
            dv[idx] = srcv[idx];
        }
    }
    for (int i = tid; i < 1350; i += 192) {
        int hh = i % 6, ii = i / 6;
        tb[hh * 228 + ii] = tbl[i];
    }
    if (tid < 64) {
        int ph = tid >> 3, pw = tid & 7;
        int gh = wh * 8 + ph, gw = ww * 8 + pw;
        int rh = gh < (H_ - 8) ? 0 : (gh < (H_ - 4) ? 1 : 2);
        int rw = gw < (W_ - 8) ? 0 : (gw < (W_ - 4) ? 1 : 2);
        ids[tid] = rh * 3 + rw;
    }

    const int rA = r, rB = r + 32;
    ull qA[16], qB[16];
    {
        const ull* qa = (const ull*)(base + (size_t)(h * 64 + rA) * 32);
        const ull* qb = (const ull*)(base + (size_t)(h * 64 + rB) * 32);
        #pragma unroll
        for (int i = 0; i < 16; i++) { qA[i] = qa[i]; qB[i] = qb[i]; }
    }
    __syncthreads();

    const int baseA = ((rA >> 3) + 7) * 15 + ((rA & 7) + 7);
    const int baseB = ((rB >> 3) + 7) * 15 + ((rB & 7) + 7);
    const int idnA = ids[rA];
    const int idnB = ids[rB];
    const float* tbh = tb + h * 228;

    float sumA = 0.f, sumB = 0.f;
    ull accA[16], accB[16];
    #pragma unroll
    for (int i = 0; i < 16; i++) { accA[i] = 0ull; accB[i] = 0ull; }

    const ulonglong2* ksr = (const ulonglong2*)(ks + h * 2048);
    const ulonglong2* vsr = (const ulonglong2*)(vs + h * 2048);

    #pragma unroll 2
    for (int m = 0; m < 64; m++) {
        const ulonglong2* kk = ksr + m * 8;
        ull dA0 = 0, dA1 = 0, dB0 = 0, dB1 = 0;
        #pragma unroll
        for (int i = 0; i < 8; i++) {
            ulonglong2 kv = kk[i];
            dA0 = ffma2(qA[2 * i],     kv.x, dA0);
            dA1 = ffma2(qA[2 * i + 1], kv.y, dA1);
            dB0 = ffma2(qB[2 * i],     kv.x, dB0);
            dB1 = ffma2(qB[2 * i + 1], kv.y, dB1);
        }
        float a0, a1, a2, a3, b0, b1, b2, b3;
        upk2(dA0, a0, a1); upk2(dA1, a2, a3);
        upk2(dB0, b0, b1); upk2(dB1, b2, b3);
        int moff = (m >> 3) * 15 + (m & 7);
        int idm  = ids[m];
        float svA = (a0 + a1) + (a2 + a3) + tbh[baseA - moff]
                    - (idnA != idm ? 100.0f : 0.0f);
        float svB = (b0 + b1) + (b2 + b3) + tbh[baseB - moff]
                    - (idnB != idm ? 100.0f : 0.0f);
        float eA = __expf(svA), eB = __expf(svB);
        sumA += eA; sumB += eB;
        ull e2A = dup2(eA), e2B = dup2(eB);
        const ulonglong2* vv = vsr + m * 8;
        #pragma unroll
        for (int i = 0; i < 8; i++) {
            ulonglong2 vx = vv[i];
            accA[2 * i]     = ffma2(e2A, vx.x, accA[2 * i]);
            accA[2 * i + 1] = ffma2(e2A, vx.y, accA[2 * i + 1]);
            accB[2 * i]     = ffma2(e2B, vx.x, accB[2 * i]);
            accB[2 * i + 1] = ffma2(e2B, vx.y, accB[2 * i + 1]);
        }
    }

    const float invA = 1.0f / sumA;
    const float invB = 1.0f / sumB;
    float* oA = g_att + ((size_t)b_ * 64 + rA) * 192 + h * 32;
    float* oB = g_att + ((size_t)b_ * 64 + rB) * 192 + h * 32;
    #pragma unroll
    for (int i = 0; i < 16; i++) {
        float xx, yy;
        upk2(accA[i], xx, yy);
        *(float2*)&oA[2 * i] = make_float2(xx * invA, yy * invA);
        upk2(accB[i], xx, yy);
        *(float2*)&oB[2 * i] = make_float2(xx * invB, yy * invB);
    }
}

// =====================================================================
// Kernel 3: output projection + window-reverse + reverse roll scatter
// grid=4608, block=256. smem: as[192][66] + wsm[192][194] = 199680 B
// =====================================================================
__global__ __launch_bounds__(256, 1)
void k_proj(const float* __restrict__ w, const float* __restrict__ bias,
            float* __restrict__ out) {
    extern __shared__ float sm[];
    float* as  = sm;               // [192][66]
    float* wsm = sm + 192 * 66;    // [192][194], later reused as res[192][66]
    __shared__ int soff[64];

    const int b_  = blockIdx.x;
    const int b   = b_ / 576;
    const int wh  = (b_ % 576) / 24;
    const int ww  = b_ % 24;
    const int tid = threadIdx.x;

    if (tid < 64) {
        int ph = tid >> 3, pw = tid & 7;
        int sh = wh * 8 + ph + SS_; if (sh >= H_) sh -= H_;
        int sw = ww * 8 + pw + SS_; if (sw >= W_) sw -= W_;
        soff[tid] = sh * W_ + sw;
    }

    const float* ab = g_att + (size_t)b_ * 64 * 192;
    #pragma unroll
    for (int i = 0; i < 48; i++) {
        int idx = tid + i * 256;
        int t = idx / 192, c = idx - t * 192;
        as[c * 66 + t] = ab[idx];
    }
    #pragma unroll
    for (int i = 0; i < 144; i++) {
        int idx = tid + i * 256;
        int o = idx / 192, k = idx - o * 192;
        wsm[k * 194 + o] = w[o * 192 + k];
    }
    __syncthreads();

    const int ty = tid >> 4, tx = tid & 15, t0 = ty * 4;

    ull acc[4][6];
    #pragma unroll
    for (int j = 0; j < 6; j++) {
        ull bb = *(const ull*)&bias[2 * tx + 32 * j];
        #pragma unroll
        for (int t = 0; t < 4; t++) acc[t][j] = bb;
    }

    #pragma unroll 2
    for (int k = 0; k < 192; k++) {
        const ull* ar = (const ull*)&as[k * 66 + t0];
        float ax, ay, az, aw;
        upk2(ar[0], ax, ay);
        upk2(ar[1], az, aw);
        ull a0 = dup2(ax), a1 = dup2(ay), a2 = dup2(az), a3 = dup2(aw);
        const ull* wr = (const ull*)&wsm[k * 194 + 2 * tx];
        #pragma unroll
        for (int j = 0; j < 6; j++) {
            ull bv = wr[16 * j];
            acc[0][j] = ffma2(a0, bv, acc[0][j]);
            acc[1][j] = ffma2(a1, bv, acc[1][j]);
            acc[2][j] = ffma2(a2, bv, acc[2][j]);
            acc[3][j] = ffma2(a3, bv, acc[3][j]);
        }
    }
    __syncthreads();   // all wsm reads done

    float* res = wsm;  // [192][66]
    #pragma unroll
    for (int j = 0; j < 6; j++) {
        int o = 2 * tx + 32 * j;
        #pragma unroll
        for (int t = 0; t < 4; t++) {
            float xx, yy;
            upk2(acc[t][j], xx, yy);
            res[o * 66 + t0 + t]       = xx;
            res[(o + 1) * 66 + t0 + t] = yy;
        }
    }
    __syncthreads();

    float* outb = out + (size_t)b * C_ * HW_;
    #pragma unroll
    for (int i = 0; i < 48; i++) {
        int idx = tid + i * 256;
        int o = idx >> 6, t = idx & 63;
        outb[o * HW_ + soff[t]] = res[o * 66 + t];
    }
}

// =====================================================================
extern "C" void kernel_launch(void* const* d_in, const int* in_sizes, int n_in,
                              void* d_out, int out_size) {
    const float* x      = (const float*)d_in[0];
    const float* qkv_w  = (const float*)d_in[1];
    const float* qkv_b  = (const float*)d_in[2];
    const float* proj_w = (const float*)d_in[3];
    const float* proj_b = (const float*)d_in[4];
    const float* tbl    = (const float*)d_in[5];
    float* out = (float*)d_out;

    cudaFuncSetAttribute(k_qkv,  cudaFuncAttributeMaxDynamicSharedMemorySize, 198144);
    cudaFuncSetAttribute(k_attn, cudaFuncAttributeMaxDynamicSharedMemorySize, 104032);
    cudaFuncSetAttribute(k_proj, cudaFuncAttributeMaxDynamicSharedMemorySize, 199680);

    k_qkv<<<NWIN, 256, 198144>>>(x, qkv_w, qkv_b);
    k_attn<<<NWIN, 192, 104032>>>(tbl);
    k_proj<<<NWIN, 256, 199680>>>(proj_w, proj_b, out);
}